// round 1
// baseline (speedup 1.0000x reference)
#include <cuda_runtime.h>
#include <math.h>

// ---------------------------------------------------------------------------
// Problem constants
// ---------------------------------------------------------------------------
#define B 2048
#define HW 64                       // input H = W = 64
#define C1 15
#define C2 30
#define P1 29                       // pooled size after conv1 (58/2)
#define P2 11                       // pooled size after conv2 (22/2, row 22 dropped)
#define IN2 29                      // conv2 input spatial
#define FC1_IN (30*11*11)           // 3630
#define FC1_OUT 200

// ---------------------------------------------------------------------------
// Scratch (static __device__ — no allocation allowed)
// ---------------------------------------------------------------------------
__device__ float g_pcen[B * HW * HW];            // 32 MB   [b][h][w]
__device__ float g_p1[B * C1 * P1 * P1];         // 103 MB  [b][c][i][j]
__device__ float g_p2[B * C2 * P2 * P2];         // 29.7 MB [b][c][i][j]
__device__ float g_fc1[B * FC1_OUT];             // 1.6 MB

// ---------------------------------------------------------------------------
// Kernel 1: PCEN.  One block per image, 64 threads (thread = h row).
// EMA recurrence runs over w (innermost, contiguous) for each (b, h).
// ---------------------------------------------------------------------------
__global__ __launch_bounds__(64) void pcen_kernel(
    const float* __restrict__ x,
    const float* __restrict__ log_s, const float* __restrict__ log_alpha,
    const float* __restrict__ log_delta, const float* __restrict__ log_r)
{
    __shared__ float sm[64 * 65];
    const int b = blockIdx.x, t = threadIdx.x;
    const float* xb = x + (size_t)b * 4096;

    for (int i = t; i < 4096; i += 64)
        sm[(i >> 6) * 65 + (i & 63)] = xb[i];

    const float s     = expf(log_s[0]);
    const float alpha = expf(log_alpha[0]);
    const float delta = expf(log_delta[0]);
    const float r     = expf(log_r[0]);
    const float oms   = 1.0f - s;
    const float dr    = powf(delta, r);
    __syncthreads();

    float* row = sm + t * 65;
    float m = 0.0f;
    for (int w = 0; w < 64; w++) {
        float xv = row[w];
        m = (w == 0) ? s * xv : oms * m + s * xv;
        float Ma = powf(m + 1e-6f, alpha);
        row[w] = powf(xv / Ma + delta, r) - dr;
    }
    __syncthreads();

    float* ob = g_pcen + (size_t)b * 4096;
    for (int i = t; i < 4096; i += 64)
        ob[i] = sm[(i >> 6) * 65 + (i & 63)];
}

// ---------------------------------------------------------------------------
// Kernel 2: conv1 (1->15, 7x7 VALID) + BN + ReLU + 2x2 maxpool.
// Block per image. Each thread computes one pooled pixel for ALL 15 channels
// (60 accumulators): per tap = 4 input LDS + 15 broadcast weight LDS + 60 FFMA.
// ---------------------------------------------------------------------------
__global__ __launch_bounds__(288) void conv1_kernel(
    const float* __restrict__ w1, const float* __restrict__ b1,
    const float* __restrict__ g,  const float* __restrict__ be,
    const float* __restrict__ mu, const float* __restrict__ va)
{
    __shared__ float inS[64 * 65];
    __shared__ float wS[C1 * 49];
    __shared__ float scS[C1], shS[C1];

    const int b = blockIdx.x, t = threadIdx.x;
    const float* src = g_pcen + (size_t)b * 4096;
    for (int i = t; i < 4096; i += 288)
        inS[(i >> 6) * 65 + (i & 63)] = src[i];
    for (int i = t; i < C1 * 49; i += 288)
        wS[i] = w1[i];
    if (t < C1) {
        float inv = g[t] * rsqrtf(va[t] + 1e-5f);
        scS[t] = inv;
        shS[t] = (b1[t] - mu[t]) * inv + be[t];
    }
    __syncthreads();

    for (int pos = t; pos < P1 * P1; pos += 288) {
        const int pi = pos / P1, pj = pos % P1;
        float acc[C1][4];
        #pragma unroll
        for (int c = 0; c < C1; c++) {
            acc[c][0] = 0.f; acc[c][1] = 0.f; acc[c][2] = 0.f; acc[c][3] = 0.f;
        }
        const float* ip = inS + (2 * pi) * 65 + 2 * pj;

        #pragma unroll 1
        for (int dy = 0; dy < 7; dy++) {
            float rA[8], rB[8];
            const float* r0 = ip + dy * 65;
            #pragma unroll
            for (int k = 0; k < 8; k++) { rA[k] = r0[k]; rB[k] = r0[65 + k]; }
            #pragma unroll
            for (int dx = 0; dx < 7; dx++) {
                #pragma unroll
                for (int c = 0; c < C1; c++) {
                    float w = wS[c * 49 + dy * 7 + dx];
                    acc[c][0] += rA[dx]     * w;
                    acc[c][1] += rA[dx + 1] * w;
                    acc[c][2] += rB[dx]     * w;
                    acc[c][3] += rB[dx + 1] * w;
                }
            }
        }
        #pragma unroll
        for (int c = 0; c < C1; c++) {
            float sc = scS[c], sh = shS[c];
            float v0 = fmaxf(acc[c][0] * sc + sh, 0.f);
            float v1 = fmaxf(acc[c][1] * sc + sh, 0.f);
            float v2 = fmaxf(acc[c][2] * sc + sh, 0.f);
            float v3 = fmaxf(acc[c][3] * sc + sh, 0.f);
            float v = fmaxf(fmaxf(v0, v1), fmaxf(v2, v3));
            g_p1[(((size_t)b * C1 + c) * P1 + pi) * P1 + pj] = v;
        }
    }
}

// ---------------------------------------------------------------------------
// Kernel 3: conv2 (15->30, 7x7 VALID) + BN + ReLU + 2x2 maxpool.
// Block per 2 images; both inputs (101KB) + all weights (88KB) in dynamic smem.
// Thread computes one pooled pixel for 10 output channels (40 accumulators).
// Only the 22x22 conv outputs the pool consumes are computed.
// ---------------------------------------------------------------------------
#define C2_SMEM_FLOATS (2 * C1 * IN2 * IN2 + C2 * C1 * 49 + 2 * C2)
__global__ __launch_bounds__(384) void conv2_kernel(
    const float* __restrict__ w2, const float* __restrict__ b2,
    const float* __restrict__ g,  const float* __restrict__ be,
    const float* __restrict__ mu, const float* __restrict__ va)
{
    extern __shared__ float sm[];
    float* inS = sm;                            // 2 * 12615
    float* wS  = sm + 2 * C1 * IN2 * IN2;       // 22050
    float* scS = wS + C2 * C1 * 49;             // 30
    float* shS = scS + C2;                      // 30

    const int t = threadIdx.x;
    const int b0 = blockIdx.x * 2;
    const float* src = g_p1 + (size_t)b0 * (C1 * IN2 * IN2);
    for (int i = t; i < 2 * C1 * IN2 * IN2; i += 384) inS[i] = src[i];
    for (int i = t; i < C2 * C1 * 49; i += 384)        wS[i] = w2[i];
    if (t < C2) {
        float inv = g[t] * rsqrtf(va[t] + 1e-5f);
        scS[t] = inv;
        shS[t] = (b2[t] - mu[t]) * inv + be[t];
    }
    __syncthreads();

    for (int item = t; item < 726; item += 384) {     // 2 img * 3 grp * 121 pos
        const int pos = item % 121;
        const int gq  = item / 121;
        const int grp = gq % 3;
        const int img = gq / 3;
        const int pi = pos / P2, pj = pos % P2;

        float acc[10][4];
        #pragma unroll
        for (int oc = 0; oc < 10; oc++) {
            acc[oc][0] = 0.f; acc[oc][1] = 0.f; acc[oc][2] = 0.f; acc[oc][3] = 0.f;
        }
        const float* ipb = inS + img * (C1 * IN2 * IN2) + (2 * pi) * IN2 + 2 * pj;
        const float* wgb = wS + (grp * 10) * (C1 * 49);

        #pragma unroll 1
        for (int ic = 0; ic < C1; ic++) {
            const float* ip = ipb + ic * (IN2 * IN2);
            const float* wc = wgb + ic * 49;
            #pragma unroll 1
            for (int dy = 0; dy < 7; dy++) {
                float rA[8], rB[8];
                const float* r0 = ip + dy * IN2;
                #pragma unroll
                for (int k = 0; k < 8; k++) { rA[k] = r0[k]; rB[k] = r0[IN2 + k]; }
                #pragma unroll
                for (int dx = 0; dx < 7; dx++) {
                    #pragma unroll
                    for (int oc = 0; oc < 10; oc++) {
                        float w = wc[oc * (C1 * 49) + dy * 7 + dx];
                        acc[oc][0] += rA[dx]     * w;
                        acc[oc][1] += rA[dx + 1] * w;
                        acc[oc][2] += rB[dx]     * w;
                        acc[oc][3] += rB[dx + 1] * w;
                    }
                }
            }
        }
        #pragma unroll
        for (int oc = 0; oc < 10; oc++) {
            const int c = grp * 10 + oc;
            float sc = scS[c], sh = shS[c];
            float v0 = fmaxf(acc[oc][0] * sc + sh, 0.f);
            float v1 = fmaxf(acc[oc][1] * sc + sh, 0.f);
            float v2 = fmaxf(acc[oc][2] * sc + sh, 0.f);
            float v3 = fmaxf(acc[oc][3] * sc + sh, 0.f);
            float v = fmaxf(fmaxf(v0, v1), fmaxf(v2, v3));
            g_p2[(((size_t)(b0 + img) * C2 + c) * P2 + pi) * P2 + pj] = v;
        }
    }
}

// ---------------------------------------------------------------------------
// Kernel 4: FC1 (2048x200 = A[2048,3630] @ W^T) + bias + ReLU.
// Tiled GEMM: grid (64 M-tiles of 32, 2 N-tiles of 128), 128 threads,
// thread tile 8 batches x 4 outputs, LDS.128 operand loads.
// ---------------------------------------------------------------------------
#define KC 30
__global__ __launch_bounds__(128) void fc1_kernel(
    const float* __restrict__ w, const float* __restrict__ bias)
{
    __shared__ __align__(16) float As[KC * 32];
    __shared__ __align__(16) float Bs[KC * 128];
    const int t = threadIdx.x;
    const int mt = blockIdx.x;      // 0..63
    const int nt = blockIdx.y;      // 0..1
    const int tx = t & 31, ty = t >> 5;

    float acc[8][4];
    #pragma unroll
    for (int i = 0; i < 8; i++)
        { acc[i][0]=0.f; acc[i][1]=0.f; acc[i][2]=0.f; acc[i][3]=0.f; }

    const float* act = g_p2 + (size_t)mt * 32 * FC1_IN;

    for (int kc = 0; kc < FC1_IN / KC; kc++) {
        for (int i = t; i < KC * 32; i += 128) {
            int bb = i / KC, k = i % KC;
            As[k * 32 + bb] = act[bb * FC1_IN + kc * KC + k];
        }
        for (int i = t; i < KC * 128; i += 128) {
            int o = i / KC, k = i % KC;
            int go = nt * 128 + o;
            Bs[k * 128 + o] = (go < FC1_OUT) ? w[(size_t)go * FC1_IN + kc * KC + k] : 0.f;
        }
        __syncthreads();
        #pragma unroll 1
        for (int k = 0; k < KC; k++) {
            float4 bv = *(const float4*)&Bs[k * 128 + tx * 4];
            float4 a0 = *(const float4*)&As[k * 32 + ty * 8];
            float4 a1 = *(const float4*)&As[k * 32 + ty * 8 + 4];
            const float av[8] = {a0.x, a0.y, a0.z, a0.w, a1.x, a1.y, a1.z, a1.w};
            #pragma unroll
            for (int i = 0; i < 8; i++) {
                acc[i][0] += av[i] * bv.x;
                acc[i][1] += av[i] * bv.y;
                acc[i][2] += av[i] * bv.z;
                acc[i][3] += av[i] * bv.w;
            }
        }
        __syncthreads();
    }
    #pragma unroll
    for (int i = 0; i < 8; i++) {
        const int bb = mt * 32 + ty * 8 + i;
        #pragma unroll
        for (int j = 0; j < 4; j++) {
            int o = nt * 128 + tx * 4 + j;
            if (o < FC1_OUT)
                g_fc1[(size_t)bb * FC1_OUT + o] = fmaxf(acc[i][j] + bias[o], 0.f);
        }
    }
}

// ---------------------------------------------------------------------------
// Kernel 5: FC2 (200 -> 2) + sigmoid. One warp per batch.
// ---------------------------------------------------------------------------
__global__ __launch_bounds__(256) void fc2_kernel(
    const float* __restrict__ w2, const float* __restrict__ b2,
    float* __restrict__ out)
{
    const int warp = threadIdx.x >> 5, lane = threadIdx.x & 31;
    const int b = blockIdx.x * 8 + warp;
    const float* a = g_fc1 + (size_t)b * FC1_OUT;
    float s0 = 0.f, s1 = 0.f;
    for (int o = lane; o < FC1_OUT; o += 32) {
        float v = a[o];
        s0 += v * w2[o];
        s1 += v * w2[FC1_OUT + o];
    }
    #pragma unroll
    for (int d = 16; d > 0; d >>= 1) {
        s0 += __shfl_xor_sync(0xFFFFFFFFu, s0, d);
        s1 += __shfl_xor_sync(0xFFFFFFFFu, s1, d);
    }
    if (lane == 0) {
        out[2 * b + 0] = 1.f / (1.f + expf(-(s0 + b2[0])));
        out[2 * b + 1] = 1.f / (1.f + expf(-(s1 + b2[1])));
    }
}

// ---------------------------------------------------------------------------
// Launch
// ---------------------------------------------------------------------------
extern "C" void kernel_launch(void* const* d_in, const int* in_sizes, int n_in,
                              void* d_out, int out_size)
{
    const float* x       = (const float*)d_in[0];
    const float* log_s   = (const float*)d_in[1];
    const float* log_a   = (const float*)d_in[2];
    const float* log_d   = (const float*)d_in[3];
    const float* log_r   = (const float*)d_in[4];
    const float* conv1_w = (const float*)d_in[5];
    const float* conv1_b = (const float*)d_in[6];
    const float* bn1_g   = (const float*)d_in[7];
    const float* bn1_b   = (const float*)d_in[8];
    const float* bn1_m   = (const float*)d_in[9];
    const float* bn1_v   = (const float*)d_in[10];
    const float* conv2_w = (const float*)d_in[11];
    const float* conv2_b = (const float*)d_in[12];
    const float* bn2_g   = (const float*)d_in[13];
    const float* bn2_b   = (const float*)d_in[14];
    const float* bn2_m   = (const float*)d_in[15];
    const float* bn2_v   = (const float*)d_in[16];
    const float* fc1_w   = (const float*)d_in[17];
    const float* fc1_b   = (const float*)d_in[18];
    const float* fc2_w   = (const float*)d_in[19];
    const float* fc2_b   = (const float*)d_in[20];
    float* out = (float*)d_out;

    pcen_kernel<<<B, 64>>>(x, log_s, log_a, log_d, log_r);
    conv1_kernel<<<B, 288>>>(conv1_w, conv1_b, bn1_g, bn1_b, bn1_m, bn1_v);

    static int smem_set = 0;
    const int smem2 = C2_SMEM_FLOATS * sizeof(float);   // ~189 KB
    if (!smem_set) {
        cudaFuncSetAttribute(conv2_kernel,
                             cudaFuncAttributeMaxDynamicSharedMemorySize, smem2);
        smem_set = 1;
    }
    conv2_kernel<<<B / 2, 384, smem2>>>(conv2_w, conv2_b, bn2_g, bn2_b, bn2_m, bn2_v);

    fc1_kernel<<<dim3(64, 2), 128>>>(fc1_w, fc1_b);
    fc2_kernel<<<B / 8, 256>>>(fc2_w, fc2_b, out);
}

// round 2
// speedup vs baseline: 1.4823x; 1.4823x over previous
#include <cuda_runtime.h>
#include <math.h>

// ---------------------------------------------------------------------------
// Problem constants
// ---------------------------------------------------------------------------
#define B 2048
#define C1 15
#define C2 30
#define P1 29                       // pooled size after conv1
#define P2 11                       // pooled size after conv2
#define IN2 29                      // conv2 input spatial
#define IN2P 32                     // padded row stride for conv2 input
#define FC1_IN (30*11*11)           // 3630
#define FC1_OUT 200
#define KSPLIT 11                   // fc1 K-split factor (121 KC-chunks / 11)

// ---------------------------------------------------------------------------
// Scratch (static __device__ — no allocation allowed)
// ---------------------------------------------------------------------------
__device__ float g_p1[B * C1 * P1 * IN2P];           // padded [b][c][29][32], 114 MB
__device__ float g_p2[B * C2 * P2 * P2];             // [b][c][11][11], 29.7 MB
__device__ float g_fc1p[KSPLIT * B * FC1_OUT];       // fc1 K-partials, 18 MB

// ---------------------------------------------------------------------------
// Kernel 1: PCEN + conv1 (1->15, 7x7) + BN + ReLU + 2x2 maxpool, fused.
// One block per image, 288 threads.
//  - image -> smem (row stride 66 for float2-aligned conv reads)
//  - 64 threads run the per-row EMA recurrence in place
//  - conv: thread = 1 pooled pixel x all 15 channels (60 accumulators)
//    weights transposed to [dy*7+dx][c] (16-pad) -> float4/float2 loads
// ---------------------------------------------------------------------------
__global__ __launch_bounds__(288) void conv1_pcen_kernel(
    const float* __restrict__ x,
    const float* __restrict__ log_s, const float* __restrict__ log_alpha,
    const float* __restrict__ log_delta, const float* __restrict__ log_r,
    const float* __restrict__ w1, const float* __restrict__ b1,
    const float* __restrict__ g,  const float* __restrict__ be,
    const float* __restrict__ mu, const float* __restrict__ va)
{
    __shared__ __align__(16) float inS[64 * 66];
    __shared__ __align__(16) float wT[49 * 16];
    __shared__ float scS[C1], shS[C1];

    const int b = blockIdx.x, t = threadIdx.x;
    const float* xb = x + (size_t)b * 4096;

    for (int i = t; i < 4096; i += 288)
        inS[(i >> 6) * 66 + (i & 63)] = xb[i];
    for (int i = t; i < C1 * 49; i += 288) {
        int c = i / 49, k = i % 49;
        wT[k * 16 + c] = w1[i];
    }
    if (t < C1) {
        float inv = g[t] * rsqrtf(va[t] + 1e-5f);
        scS[t] = inv;
        shS[t] = (b1[t] - mu[t]) * inv + be[t];
    }
    __syncthreads();

    // PCEN recurrence: thread t < 64 owns row h = t, loop over w
    if (t < 64) {
        const float s     = expf(log_s[0]);
        const float alpha = expf(log_alpha[0]);
        const float delta = expf(log_delta[0]);
        const float r     = expf(log_r[0]);
        const float oms   = 1.0f - s;
        const float dr    = powf(delta, r);
        float* row = inS + t * 66;
        float m = 0.0f;
        #pragma unroll 4
        for (int w = 0; w < 64; w++) {
            float xv = row[w];
            m = (w == 0) ? s * xv : oms * m + s * xv;
            float Ma = __powf(m + 1e-6f, alpha);
            row[w] = __powf(__fdividef(xv, Ma) + delta, r) - dr;
        }
    }
    __syncthreads();

    for (int pos = t; pos < P1 * P1; pos += 288) {
        const int pi = pos / P1, pj = pos % P1;
        float acc[C1][4];
        #pragma unroll
        for (int c = 0; c < C1; c++) {
            acc[c][0] = 0.f; acc[c][1] = 0.f; acc[c][2] = 0.f; acc[c][3] = 0.f;
        }
        const float* ip = inS + (2 * pi) * 66 + 2 * pj;   // even offset

        #pragma unroll 1
        for (int dy = 0; dy < 7; dy++) {
            float rA[8], rB[8];
            const float* r0 = ip + dy * 66;
            #pragma unroll
            for (int k = 0; k < 4; k++) {
                float2 a = *(const float2*)&r0[2 * k];
                float2 bq = *(const float2*)&r0[66 + 2 * k];
                rA[2 * k] = a.x;  rA[2 * k + 1] = a.y;
                rB[2 * k] = bq.x; rB[2 * k + 1] = bq.y;
            }
            #pragma unroll
            for (int dx = 0; dx < 7; dx++) {
                const float* wp = wT + (dy * 7 + dx) * 16;
                float wv[15];
                float4 w0 = *(const float4*)&wp[0];
                float4 w1v = *(const float4*)&wp[4];
                float4 w2v = *(const float4*)&wp[8];
                float2 w3 = *(const float2*)&wp[12];
                wv[0]=w0.x; wv[1]=w0.y; wv[2]=w0.z; wv[3]=w0.w;
                wv[4]=w1v.x; wv[5]=w1v.y; wv[6]=w1v.z; wv[7]=w1v.w;
                wv[8]=w2v.x; wv[9]=w2v.y; wv[10]=w2v.z; wv[11]=w2v.w;
                wv[12]=w3.x; wv[13]=w3.y; wv[14]=wp[14];
                #pragma unroll
                for (int c = 0; c < C1; c++) {
                    acc[c][0] += rA[dx]     * wv[c];
                    acc[c][1] += rA[dx + 1] * wv[c];
                    acc[c][2] += rB[dx]     * wv[c];
                    acc[c][3] += rB[dx + 1] * wv[c];
                }
            }
        }
        float* ob = g_p1 + (size_t)b * (C1 * P1 * IN2P) + pi * IN2P + pj;
        #pragma unroll
        for (int c = 0; c < C1; c++) {
            float sc = scS[c], sh = shS[c];
            float v0 = fmaxf(acc[c][0] * sc + sh, 0.f);
            float v1 = fmaxf(acc[c][1] * sc + sh, 0.f);
            float v2 = fmaxf(acc[c][2] * sc + sh, 0.f);
            float v3 = fmaxf(acc[c][3] * sc + sh, 0.f);
            ob[c * (P1 * IN2P)] = fmaxf(fmaxf(v0, v1), fmaxf(v2, v3));
        }
    }
}

// ---------------------------------------------------------------------------
// Kernel 2: conv2 (15->30, 7x7) + BN + ReLU + 2x2 maxpool.
// One block per image, 384 threads, dynamic smem:
//   input  [15][29][32] padded (float2-aligned reads)
//   weights transposed [ic*49+k][oc] (30 contiguous -> float2 loads)
// Thread = 1 pooled pixel x 10 output channels (40 accumulators).
// ---------------------------------------------------------------------------
#define C2_IN_FLOATS  (C1 * P1 * IN2P)                 // 13920
#define C2_W_FLOATS   (C2 * C1 * 49)                   // 22050
#define C2_SMEM_FLOATS (C2_IN_FLOATS + C2_W_FLOATS + 2 * C2)
__global__ __launch_bounds__(384) void conv2_kernel(
    const float* __restrict__ w2, const float* __restrict__ b2,
    const float* __restrict__ g,  const float* __restrict__ be,
    const float* __restrict__ mu, const float* __restrict__ va)
{
    extern __shared__ __align__(16) float sm[];
    float* inS = sm;                       // 13920
    float* wT  = sm + C2_IN_FLOATS;        // 22050: [ic*49+k][oc]
    float* scS = wT + C2_W_FLOATS;
    float* shS = scS + C2;

    const int t = threadIdx.x;
    const int b = blockIdx.x;

    {
        const float4* s4 = (const float4*)(g_p1 + (size_t)b * C2_IN_FLOATS);
        float4* d4 = (float4*)inS;
        for (int i = t; i < C2_IN_FLOATS / 4; i += 384) d4[i] = s4[i];
    }
    for (int i = t; i < C2_W_FLOATS; i += 384) {
        int oc = i / 735, rem = i % 735;
        wT[rem * 30 + oc] = w2[i];
    }
    if (t < C2) {
        float inv = g[t] * rsqrtf(va[t] + 1e-5f);
        scS[t] = inv;
        shS[t] = (b2[t] - mu[t]) * inv + be[t];
    }
    __syncthreads();

    const int item = t;                     // 363 items: 3 grp x 121 pos
    if (item < 363) {
        const int pos = item % 121;
        const int grp = item / 121;
        const int pi = pos / P2, pj = pos % P2;

        float acc[10][4];
        #pragma unroll
        for (int oc = 0; oc < 10; oc++) {
            acc[oc][0] = 0.f; acc[oc][1] = 0.f; acc[oc][2] = 0.f; acc[oc][3] = 0.f;
        }
        const float* ipb = inS + (2 * pi) * IN2P + 2 * pj;   // even offset
        const int ocBase = grp * 10;                          // even -> 8B aligned

        #pragma unroll 1
        for (int ic = 0; ic < C1; ic++) {
            const float* ip = ipb + ic * (P1 * IN2P);
            const float* wc = wT + (ic * 49) * 30 + ocBase;
            #pragma unroll 1
            for (int dy = 0; dy < 7; dy++) {
                float rA[8], rB[8];
                const float* r0 = ip + dy * IN2P;
                #pragma unroll
                for (int k = 0; k < 4; k++) {
                    float2 a = *(const float2*)&r0[2 * k];
                    float2 bq = *(const float2*)&r0[IN2P + 2 * k];
                    rA[2 * k] = a.x;  rA[2 * k + 1] = a.y;
                    rB[2 * k] = bq.x; rB[2 * k + 1] = bq.y;
                }
                #pragma unroll
                for (int dx = 0; dx < 7; dx++) {
                    const float* wp = wc + (dy * 7 + dx) * 30;
                    float wv[10];
                    #pragma unroll
                    for (int q = 0; q < 5; q++) {
                        float2 wq = *(const float2*)&wp[2 * q];
                        wv[2 * q] = wq.x; wv[2 * q + 1] = wq.y;
                    }
                    #pragma unroll
                    for (int oc = 0; oc < 10; oc++) {
                        acc[oc][0] += rA[dx]     * wv[oc];
                        acc[oc][1] += rA[dx + 1] * wv[oc];
                        acc[oc][2] += rB[dx]     * wv[oc];
                        acc[oc][3] += rB[dx + 1] * wv[oc];
                    }
                }
            }
        }
        #pragma unroll
        for (int oc = 0; oc < 10; oc++) {
            const int c = ocBase + oc;
            float sc = scS[c], sh = shS[c];
            float v0 = fmaxf(acc[oc][0] * sc + sh, 0.f);
            float v1 = fmaxf(acc[oc][1] * sc + sh, 0.f);
            float v2 = fmaxf(acc[oc][2] * sc + sh, 0.f);
            float v3 = fmaxf(acc[oc][3] * sc + sh, 0.f);
            float v = fmaxf(fmaxf(v0, v1), fmaxf(v2, v3));
            g_p2[(((size_t)b * C2 + c) * P2 + pi) * P2 + pj] = v;
        }
    }
}

// ---------------------------------------------------------------------------
// Kernel 3: FC1 partial GEMM with K-split (deterministic, no atomics).
// Grid (64 M-tiles of 32, 2 N-tiles of 128, 11 K-slices of 330).
// Bias + ReLU applied in fc2 after partial summation.
// ---------------------------------------------------------------------------
#define KC 30
__global__ __launch_bounds__(128) void fc1_kernel(
    const float* __restrict__ w)
{
    __shared__ __align__(16) float As[KC * 32];
    __shared__ __align__(16) float Bs[KC * 128];
    const int t = threadIdx.x;
    const int mt = blockIdx.x;      // 0..63
    const int nt = blockIdx.y;      // 0..1
    const int kz = blockIdx.z;      // 0..10
    const int tx = t & 31, ty = t >> 5;

    float acc[8][4];
    #pragma unroll
    for (int i = 0; i < 8; i++)
        { acc[i][0]=0.f; acc[i][1]=0.f; acc[i][2]=0.f; acc[i][3]=0.f; }

    const float* act = g_p2 + (size_t)mt * 32 * FC1_IN;
    const int kc0 = kz * 11;

    for (int kc = kc0; kc < kc0 + 11; kc++) {
        for (int i = t; i < KC * 32; i += 128) {
            int bb = i / KC, k = i % KC;
            As[k * 32 + bb] = act[bb * FC1_IN + kc * KC + k];
        }
        for (int i = t; i < KC * 128; i += 128) {
            int o = i / KC, k = i % KC;
            int go = nt * 128 + o;
            Bs[k * 128 + o] = (go < FC1_OUT) ? w[(size_t)go * FC1_IN + kc * KC + k] : 0.f;
        }
        __syncthreads();
        #pragma unroll 1
        for (int k = 0; k < KC; k++) {
            float4 bv = *(const float4*)&Bs[k * 128 + tx * 4];
            float4 a0 = *(const float4*)&As[k * 32 + ty * 8];
            float4 a1 = *(const float4*)&As[k * 32 + ty * 8 + 4];
            const float av[8] = {a0.x, a0.y, a0.z, a0.w, a1.x, a1.y, a1.z, a1.w};
            #pragma unroll
            for (int i = 0; i < 8; i++) {
                acc[i][0] += av[i] * bv.x;
                acc[i][1] += av[i] * bv.y;
                acc[i][2] += av[i] * bv.z;
                acc[i][3] += av[i] * bv.w;
            }
        }
        __syncthreads();
    }
    float* dst = g_fc1p + (size_t)kz * B * FC1_OUT;
    #pragma unroll
    for (int i = 0; i < 8; i++) {
        const int bb = mt * 32 + ty * 8 + i;
        #pragma unroll
        for (int j = 0; j < 4; j++) {
            int o = nt * 128 + tx * 4 + j;
            if (o < FC1_OUT)
                dst[(size_t)bb * FC1_OUT + o] = acc[i][j];
        }
    }
}

// ---------------------------------------------------------------------------
// Kernel 4: sum K-partials + bias + ReLU, then FC2 (200 -> 2) + sigmoid.
// One warp per batch.
// ---------------------------------------------------------------------------
__global__ __launch_bounds__(256) void fc2_kernel(
    const float* __restrict__ fc1b,
    const float* __restrict__ w2, const float* __restrict__ b2,
    float* __restrict__ out)
{
    const int warp = threadIdx.x >> 5, lane = threadIdx.x & 31;
    const int b = blockIdx.x * 8 + warp;
    const size_t PS = (size_t)B * FC1_OUT;
    const float* base = g_fc1p + (size_t)b * FC1_OUT;
    float s0 = 0.f, s1 = 0.f;
    for (int o = lane; o < FC1_OUT; o += 32) {
        float v = fc1b[o];
        #pragma unroll
        for (int p = 0; p < KSPLIT; p++)
            v += base[p * PS + o];
        v = fmaxf(v, 0.f);
        s0 += v * w2[o];
        s1 += v * w2[FC1_OUT + o];
    }
    #pragma unroll
    for (int d = 16; d > 0; d >>= 1) {
        s0 += __shfl_xor_sync(0xFFFFFFFFu, s0, d);
        s1 += __shfl_xor_sync(0xFFFFFFFFu, s1, d);
    }
    if (lane == 0) {
        out[2 * b + 0] = 1.f / (1.f + expf(-(s0 + b2[0])));
        out[2 * b + 1] = 1.f / (1.f + expf(-(s1 + b2[1])));
    }
}

// ---------------------------------------------------------------------------
// Launch
// ---------------------------------------------------------------------------
extern "C" void kernel_launch(void* const* d_in, const int* in_sizes, int n_in,
                              void* d_out, int out_size)
{
    const float* x       = (const float*)d_in[0];
    const float* log_s   = (const float*)d_in[1];
    const float* log_a   = (const float*)d_in[2];
    const float* log_d   = (const float*)d_in[3];
    const float* log_r   = (const float*)d_in[4];
    const float* conv1_w = (const float*)d_in[5];
    const float* conv1_b = (const float*)d_in[6];
    const float* bn1_g   = (const float*)d_in[7];
    const float* bn1_b   = (const float*)d_in[8];
    const float* bn1_m   = (const float*)d_in[9];
    const float* bn1_v   = (const float*)d_in[10];
    const float* conv2_w = (const float*)d_in[11];
    const float* conv2_b = (const float*)d_in[12];
    const float* bn2_g   = (const float*)d_in[13];
    const float* bn2_b   = (const float*)d_in[14];
    const float* bn2_m   = (const float*)d_in[15];
    const float* bn2_v   = (const float*)d_in[16];
    const float* fc1_w   = (const float*)d_in[17];
    const float* fc1_b   = (const float*)d_in[18];
    const float* fc2_w   = (const float*)d_in[19];
    const float* fc2_b   = (const float*)d_in[20];
    float* out = (float*)d_out;

    conv1_pcen_kernel<<<B, 288>>>(x, log_s, log_a, log_d, log_r,
                                  conv1_w, conv1_b, bn1_g, bn1_b, bn1_m, bn1_v);

    static int smem_set = 0;
    const int smem2 = C2_SMEM_FLOATS * sizeof(float);   // ~141 KB
    if (!smem_set) {
        cudaFuncSetAttribute(conv2_kernel,
                             cudaFuncAttributeMaxDynamicSharedMemorySize, smem2);
        smem_set = 1;
    }
    conv2_kernel<<<B, 384, smem2>>>(conv2_w, conv2_b, bn2_g, bn2_b, bn2_m, bn2_v);

    fc1_kernel<<<dim3(64, 2, KSPLIT), 128>>>(fc1_w);
    fc2_kernel<<<B / 8, 256>>>(fc1_b, fc2_w, fc2_b, out);
}

// round 3
// speedup vs baseline: 1.5145x; 1.0217x over previous
#include <cuda_runtime.h>
#include <math.h>

// ---------------------------------------------------------------------------
// Problem constants
// ---------------------------------------------------------------------------
#define B 2048
#define C1 15
#define C2 30
#define P1 29                       // pooled size after conv1
#define P2 11                       // pooled size after conv2
#define IN2 29                      // conv2 input spatial
#define IN2P 32                     // padded row stride for conv2 input
#define FC1_IN (30*11*11)           // 3630
#define FC1_OUT 200
#define KSPLIT 11                   // fc1 K-split factor

typedef unsigned long long ull;

// ---------------------------------------------------------------------------
// Packed f32x2 helpers (sm_103a): one FFMA2 = two independent fp32 FMAs.
// ---------------------------------------------------------------------------
__device__ __forceinline__ ull pack_dup(float v) {
    ull r; unsigned int u = __float_as_uint(v);
    asm("mov.b64 %0, {%1, %2};" : "=l"(r) : "r"(u), "r"(u));
    return r;
}
__device__ __forceinline__ void ffma2(ull& d, ull a, ull b) {
    asm("fma.rn.f32x2 %0, %1, %2, %3;" : "=l"(d) : "l"(a), "l"(b), "l"(d));
}
__device__ __forceinline__ float2 unpack2(ull p) {
    unsigned int lo, hi;
    asm("mov.b64 {%0, %1}, %2;" : "=r"(lo), "=r"(hi) : "l"(p));
    return make_float2(__uint_as_float(lo), __uint_as_float(hi));
}

// ---------------------------------------------------------------------------
// Scratch (static __device__ — no allocation allowed)
// ---------------------------------------------------------------------------
__device__ float g_p1[B * C1 * P1 * IN2P];           // padded [b][c][29][32]
__device__ float g_p2[B * C2 * P2 * P2];             // [b][c][11][11]
__device__ float g_fc1p[KSPLIT * B * FC1_OUT];       // fc1 K-partials

// ---------------------------------------------------------------------------
// Kernel 1: PCEN + conv1 (1->16ch padded, 7x7) + BN + ReLU + 2x2 maxpool.
// One block per image, 288 threads. Conv math in packed f32x2 over channel
// pairs: weight pair {w[c], w[c+1]} is one ld.shared.b64.
// ---------------------------------------------------------------------------
__global__ __launch_bounds__(288) void conv1_pcen_kernel(
    const float* __restrict__ x,
    const float* __restrict__ log_s, const float* __restrict__ log_alpha,
    const float* __restrict__ log_delta, const float* __restrict__ log_r,
    const float* __restrict__ w1, const float* __restrict__ b1,
    const float* __restrict__ g,  const float* __restrict__ be,
    const float* __restrict__ mu, const float* __restrict__ va)
{
    __shared__ __align__(16) float inS[64 * 66];
    __shared__ __align__(16) float wT[49 * 16];      // [k][c16], c15 = 0
    __shared__ float scS[C1], shS[C1];

    const int b = blockIdx.x, t = threadIdx.x;
    const float* xb = x + (size_t)b * 4096;

    for (int i = t; i < 4096; i += 288)
        inS[(i >> 6) * 66 + (i & 63)] = xb[i];
    for (int i = t; i < 49 * 16; i += 288) {
        int k = i >> 4, c = i & 15;
        wT[i] = (c < C1) ? w1[c * 49 + k] : 0.f;
    }
    if (t < C1) {
        float inv = g[t] * rsqrtf(va[t] + 1e-5f);
        scS[t] = inv;
        shS[t] = (b1[t] - mu[t]) * inv + be[t];
    }
    __syncthreads();

    // PCEN recurrence: thread t < 64 owns row h = t, loop over w
    if (t < 64) {
        const float s     = expf(log_s[0]);
        const float alpha = expf(log_alpha[0]);
        const float delta = expf(log_delta[0]);
        const float r     = expf(log_r[0]);
        const float oms   = 1.0f - s;
        const float dr    = powf(delta, r);
        float* row = inS + t * 66;
        float m = 0.0f;
        #pragma unroll 4
        for (int w = 0; w < 64; w++) {
            float xv = row[w];
            m = (w == 0) ? s * xv : oms * m + s * xv;
            float Ma = __powf(m + 1e-6f, alpha);
            row[w] = __powf(__fdividef(xv, Ma) + delta, r) - dr;
        }
    }
    __syncthreads();

    for (int pos = t; pos < P1 * P1; pos += 288) {
        const int pi = pos / P1, pj = pos % P1;
        ull acc[8][4];
        #pragma unroll
        for (int q = 0; q < 8; q++)
            { acc[q][0]=0ull; acc[q][1]=0ull; acc[q][2]=0ull; acc[q][3]=0ull; }
        const float* ip = inS + (2 * pi) * 66 + 2 * pj;   // even offset

        #pragma unroll 1
        for (int dy = 0; dy < 7; dy++) {
            float rA[8], rB[8];
            const float* r0 = ip + dy * 66;
            #pragma unroll
            for (int k = 0; k < 4; k++) {
                float2 a = *(const float2*)&r0[2 * k];
                float2 bq = *(const float2*)&r0[66 + 2 * k];
                rA[2 * k] = a.x;  rA[2 * k + 1] = a.y;
                rB[2 * k] = bq.x; rB[2 * k + 1] = bq.y;
            }
            ull dA[8], dB[8];
            #pragma unroll
            for (int k = 0; k < 8; k++) { dA[k] = pack_dup(rA[k]); dB[k] = pack_dup(rB[k]); }
            #pragma unroll
            for (int dx = 0; dx < 7; dx++) {
                const ull* wq = (const ull*)(wT + (dy * 7 + dx) * 16);
                #pragma unroll
                for (int q = 0; q < 8; q++) {
                    ull w = wq[q];
                    ffma2(acc[q][0], dA[dx],     w);
                    ffma2(acc[q][1], dA[dx + 1], w);
                    ffma2(acc[q][2], dB[dx],     w);
                    ffma2(acc[q][3], dB[dx + 1], w);
                }
            }
        }
        float* ob = g_p1 + (size_t)b * (C1 * P1 * IN2P) + pi * IN2P + pj;
        #pragma unroll
        for (int q = 0; q < 8; q++) {
            float2 v0 = unpack2(acc[q][0]);
            float2 v1 = unpack2(acc[q][1]);
            float2 v2 = unpack2(acc[q][2]);
            float2 v3 = unpack2(acc[q][3]);
            const int c0 = 2 * q, c1 = 2 * q + 1;
            {
                float sc = scS[c0], sh = shS[c0];
                float a0 = fmaxf(v0.x * sc + sh, 0.f);
                float a1 = fmaxf(v1.x * sc + sh, 0.f);
                float a2 = fmaxf(v2.x * sc + sh, 0.f);
                float a3 = fmaxf(v3.x * sc + sh, 0.f);
                ob[c0 * (P1 * IN2P)] = fmaxf(fmaxf(a0, a1), fmaxf(a2, a3));
            }
            if (c1 < C1) {
                float sc = scS[c1], sh = shS[c1];
                float a0 = fmaxf(v0.y * sc + sh, 0.f);
                float a1 = fmaxf(v1.y * sc + sh, 0.f);
                float a2 = fmaxf(v2.y * sc + sh, 0.f);
                float a3 = fmaxf(v3.y * sc + sh, 0.f);
                ob[c1 * (P1 * IN2P)] = fmaxf(fmaxf(a0, a1), fmaxf(a2, a3));
            }
        }
    }
}

// ---------------------------------------------------------------------------
// Kernel 2: conv2 (15->30, 7x7) + BN + ReLU + 2x2 maxpool, packed f32x2.
// One block per image, 384 threads. Thread = 1 pooled pixel x 10 output
// channels = 5 channel-pairs x 4 positions of packed accumulators.
// ---------------------------------------------------------------------------
#define C2_IN_FLOATS  (C1 * P1 * IN2P)                 // 13920
#define C2_W_FLOATS   (C2 * C1 * 49)                   // 22050
#define C2_SMEM_FLOATS (C2_IN_FLOATS + C2_W_FLOATS + 2 * C2)
__global__ __launch_bounds__(384) void conv2_kernel(
    const float* __restrict__ w2, const float* __restrict__ b2,
    const float* __restrict__ g,  const float* __restrict__ be,
    const float* __restrict__ mu, const float* __restrict__ va)
{
    extern __shared__ __align__(16) float sm[];
    float* inS = sm;                       // 13920
    float* wT  = sm + C2_IN_FLOATS;        // 22050: [ic*49+k][oc]
    float* scS = wT + C2_W_FLOATS;
    float* shS = scS + C2;

    const int t = threadIdx.x;
    const int b = blockIdx.x;

    {
        const float4* s4 = (const float4*)(g_p1 + (size_t)b * C2_IN_FLOATS);
        float4* d4 = (float4*)inS;
        for (int i = t; i < C2_IN_FLOATS / 4; i += 384) d4[i] = s4[i];
    }
    for (int i = t; i < C2_W_FLOATS; i += 384) {
        int oc = i / 735, rem = i % 735;
        wT[rem * 30 + oc] = w2[i];
    }
    if (t < C2) {
        float inv = g[t] * rsqrtf(va[t] + 1e-5f);
        scS[t] = inv;
        shS[t] = (b2[t] - mu[t]) * inv + be[t];
    }
    __syncthreads();

    const int item = t;                     // 363 items: 3 grp x 121 pos
    if (item < 363) {
        const int pos = item % 121;
        const int grp = item / 121;
        const int pi = pos / P2, pj = pos % P2;

        ull acc[5][4];
        #pragma unroll
        for (int q = 0; q < 5; q++)
            { acc[q][0]=0ull; acc[q][1]=0ull; acc[q][2]=0ull; acc[q][3]=0ull; }
        const float* ipb = inS + (2 * pi) * IN2P + 2 * pj;   // even offset
        const int ocBase = grp * 10;                          // even -> 8B aligned

        #pragma unroll 1
        for (int ic = 0; ic < C1; ic++) {
            const float* ip = ipb + ic * (P1 * IN2P);
            const float* wc = wT + (ic * 49) * 30 + ocBase;
            #pragma unroll 1
            for (int dy = 0; dy < 7; dy++) {
                float rA[8], rB[8];
                const float* r0 = ip + dy * IN2P;
                #pragma unroll
                for (int k = 0; k < 4; k++) {
                    float2 a = *(const float2*)&r0[2 * k];
                    float2 bq = *(const float2*)&r0[IN2P + 2 * k];
                    rA[2 * k] = a.x;  rA[2 * k + 1] = a.y;
                    rB[2 * k] = bq.x; rB[2 * k + 1] = bq.y;
                }
                ull dA[8], dB[8];
                #pragma unroll
                for (int k = 0; k < 8; k++) { dA[k] = pack_dup(rA[k]); dB[k] = pack_dup(rB[k]); }
                #pragma unroll
                for (int dx = 0; dx < 7; dx++) {
                    const ull* wq = (const ull*)(wc + (dy * 7 + dx) * 30);
                    #pragma unroll
                    for (int q = 0; q < 5; q++) {
                        ull w = wq[q];
                        ffma2(acc[q][0], dA[dx],     w);
                        ffma2(acc[q][1], dA[dx + 1], w);
                        ffma2(acc[q][2], dB[dx],     w);
                        ffma2(acc[q][3], dB[dx + 1], w);
                    }
                }
            }
        }
        #pragma unroll
        for (int q = 0; q < 5; q++) {
            float2 v0 = unpack2(acc[q][0]);
            float2 v1 = unpack2(acc[q][1]);
            float2 v2 = unpack2(acc[q][2]);
            float2 v3 = unpack2(acc[q][3]);
            const int c0 = ocBase + 2 * q, c1 = c0 + 1;
            {
                float sc = scS[c0], sh = shS[c0];
                float a0 = fmaxf(v0.x * sc + sh, 0.f);
                float a1 = fmaxf(v1.x * sc + sh, 0.f);
                float a2 = fmaxf(v2.x * sc + sh, 0.f);
                float a3 = fmaxf(v3.x * sc + sh, 0.f);
                g_p2[(((size_t)b * C2 + c0) * P2 + pi) * P2 + pj] =
                    fmaxf(fmaxf(a0, a1), fmaxf(a2, a3));
            }
            {
                float sc = scS[c1], sh = shS[c1];
                float a0 = fmaxf(v0.y * sc + sh, 0.f);
                float a1 = fmaxf(v1.y * sc + sh, 0.f);
                float a2 = fmaxf(v2.y * sc + sh, 0.f);
                float a3 = fmaxf(v3.y * sc + sh, 0.f);
                g_p2[(((size_t)b * C2 + c1) * P2 + pi) * P2 + pj] =
                    fmaxf(fmaxf(a0, a1), fmaxf(a2, a3));
            }
        }
    }
}

// ---------------------------------------------------------------------------
// Kernel 3: FC1 partial GEMM with K-split (deterministic, no atomics).
// ---------------------------------------------------------------------------
#define KC 30
__global__ __launch_bounds__(128) void fc1_kernel(
    const float* __restrict__ w)
{
    __shared__ __align__(16) float As[KC * 32];
    __shared__ __align__(16) float Bs[KC * 128];
    const int t = threadIdx.x;
    const int mt = blockIdx.x;      // 0..63
    const int nt = blockIdx.y;      // 0..1
    const int kz = blockIdx.z;      // 0..10
    const int tx = t & 31, ty = t >> 5;

    float acc[8][4];
    #pragma unroll
    for (int i = 0; i < 8; i++)
        { acc[i][0]=0.f; acc[i][1]=0.f; acc[i][2]=0.f; acc[i][3]=0.f; }

    const float* act = g_p2 + (size_t)mt * 32 * FC1_IN;
    const int kc0 = kz * 11;

    for (int kc = kc0; kc < kc0 + 11; kc++) {
        for (int i = t; i < KC * 32; i += 128) {
            int bb = i / KC, k = i % KC;
            As[k * 32 + bb] = act[bb * FC1_IN + kc * KC + k];
        }
        for (int i = t; i < KC * 128; i += 128) {
            int o = i / KC, k = i % KC;
            int go = nt * 128 + o;
            Bs[k * 128 + o] = (go < FC1_OUT) ? w[(size_t)go * FC1_IN + kc * KC + k] : 0.f;
        }
        __syncthreads();
        #pragma unroll 1
        for (int k = 0; k < KC; k++) {
            float4 bv = *(const float4*)&Bs[k * 128 + tx * 4];
            float4 a0 = *(const float4*)&As[k * 32 + ty * 8];
            float4 a1 = *(const float4*)&As[k * 32 + ty * 8 + 4];
            const float av[8] = {a0.x, a0.y, a0.z, a0.w, a1.x, a1.y, a1.z, a1.w};
            #pragma unroll
            for (int i = 0; i < 8; i++) {
                acc[i][0] += av[i] * bv.x;
                acc[i][1] += av[i] * bv.y;
                acc[i][2] += av[i] * bv.z;
                acc[i][3] += av[i] * bv.w;
            }
        }
        __syncthreads();
    }
    float* dst = g_fc1p + (size_t)kz * B * FC1_OUT;
    #pragma unroll
    for (int i = 0; i < 8; i++) {
        const int bb = mt * 32 + ty * 8 + i;
        #pragma unroll
        for (int j = 0; j < 4; j++) {
            int o = nt * 128 + tx * 4 + j;
            if (o < FC1_OUT)
                dst[(size_t)bb * FC1_OUT + o] = acc[i][j];
        }
    }
}

// ---------------------------------------------------------------------------
// Kernel 4: sum K-partials + bias + ReLU, then FC2 (200 -> 2) + sigmoid.
// ---------------------------------------------------------------------------
__global__ __launch_bounds__(256) void fc2_kernel(
    const float* __restrict__ fc1b,
    const float* __restrict__ w2, const float* __restrict__ b2,
    float* __restrict__ out)
{
    const int warp = threadIdx.x >> 5, lane = threadIdx.x & 31;
    const int b = blockIdx.x * 8 + warp;
    const size_t PS = (size_t)B * FC1_OUT;
    const float* base = g_fc1p + (size_t)b * FC1_OUT;
    float s0 = 0.f, s1 = 0.f;
    for (int o = lane; o < FC1_OUT; o += 32) {
        float v = fc1b[o];
        #pragma unroll
        for (int p = 0; p < KSPLIT; p++)
            v += base[p * PS + o];
        v = fmaxf(v, 0.f);
        s0 += v * w2[o];
        s1 += v * w2[FC1_OUT + o];
    }
    #pragma unroll
    for (int d = 16; d > 0; d >>= 1) {
        s0 += __shfl_xor_sync(0xFFFFFFFFu, s0, d);
        s1 += __shfl_xor_sync(0xFFFFFFFFu, s1, d);
    }
    if (lane == 0) {
        out[2 * b + 0] = 1.f / (1.f + expf(-(s0 + b2[0])));
        out[2 * b + 1] = 1.f / (1.f + expf(-(s1 + b2[1])));
    }
}

// ---------------------------------------------------------------------------
// Launch
// ---------------------------------------------------------------------------
extern "C" void kernel_launch(void* const* d_in, const int* in_sizes, int n_in,
                              void* d_out, int out_size)
{
    const float* x       = (const float*)d_in[0];
    const float* log_s   = (const float*)d_in[1];
    const float* log_a   = (const float*)d_in[2];
    const float* log_d   = (const float*)d_in[3];
    const float* log_r   = (const float*)d_in[4];
    const float* conv1_w = (const float*)d_in[5];
    const float* conv1_b = (const float*)d_in[6];
    const float* bn1_g   = (const float*)d_in[7];
    const float* bn1_b   = (const float*)d_in[8];
    const float* bn1_m   = (const float*)d_in[9];
    const float* bn1_v   = (const float*)d_in[10];
    const float* conv2_w = (const float*)d_in[11];
    const float* conv2_b = (const float*)d_in[12];
    const float* bn2_g   = (const float*)d_in[13];
    const float* bn2_b   = (const float*)d_in[14];
    const float* bn2_m   = (const float*)d_in[15];
    const float* bn2_v   = (const float*)d_in[16];
    const float* fc1_w   = (const float*)d_in[17];
    const float* fc1_b   = (const float*)d_in[18];
    const float* fc2_w   = (const float*)d_in[19];
    const float* fc2_b   = (const float*)d_in[20];
    float* out = (float*)d_out;

    conv1_pcen_kernel<<<B, 288>>>(x, log_s, log_a, log_d, log_r,
                                  conv1_w, conv1_b, bn1_g, bn1_b, bn1_m, bn1_v);

    static int smem_set = 0;
    const int smem2 = C2_SMEM_FLOATS * sizeof(float);   // ~141 KB
    if (!smem_set) {
        cudaFuncSetAttribute(conv2_kernel,
                             cudaFuncAttributeMaxDynamicSharedMemorySize, smem2);
        smem_set = 1;
    }
    conv2_kernel<<<B, 384, smem2>>>(conv2_w, conv2_b, bn2_g, bn2_b, bn2_m, bn2_v);

    fc1_kernel<<<dim3(64, 2, KSPLIT), 128>>>(fc1_w);
    fc2_kernel<<<B / 8, 256>>>(fc1_b, fc2_w, fc2_b, out);
}